// round 16
// baseline (speedup 1.0000x reference)
#include <cuda_runtime.h>
#include <cuda_fp16.h>
#include <math.h>
#include <math_constants.h>
#include <cstdint>

#define L_DIM 2048
#define S_DIM 2048
#define B_DIM 2
#define E_DIM 1024
#define H_DIM 16
#define HD    64
#define M_ROWS (L_DIM * B_DIM)   // 4096

// ============================ helpers ============================
__device__ __forceinline__ uint32_t smem_to_u32(const void* p) {
    uint32_t a;
    asm("{ .reg .u64 t; cvta.to.shared.u64 t, %1; cvt.u32.u64 %0, t; }" : "=r"(a) : "l"(p));
    return a;
}
__device__ __forceinline__ void cp_async16(uint32_t dst, const void* src) {
    asm volatile("cp.async.cg.shared.global [%0], [%1], 16;" :: "r"(dst), "l"(src));
}
#define CP_COMMIT() asm volatile("cp.async.commit_group;" ::: "memory")
#define CP_WAIT(n)  asm volatile("cp.async.wait_group %0;" :: "n"(n) : "memory")

__device__ __forceinline__ void ldmatrix_x4(uint32_t& r0, uint32_t& r1,
                                            uint32_t& r2, uint32_t& r3, uint32_t addr) {
    asm volatile("ldmatrix.sync.aligned.m8n8.x4.shared.b16 {%0,%1,%2,%3}, [%4];"
                 : "=r"(r0), "=r"(r1), "=r"(r2), "=r"(r3) : "r"(addr));
}
__device__ __forceinline__ void ldmatrix_x4_trans(uint32_t& r0, uint32_t& r1,
                                                  uint32_t& r2, uint32_t& r3, uint32_t addr) {
    asm volatile("ldmatrix.sync.aligned.m8n8.x4.trans.shared.b16 {%0,%1,%2,%3}, [%4];"
                 : "=r"(r0), "=r"(r1), "=r"(r2), "=r"(r3) : "r"(addr));
}
__device__ __forceinline__ void mma_f16(float* d, const uint32_t* a, const uint32_t* b) {
    asm volatile(
        "mma.sync.aligned.m16n8k16.row.col.f32.f16.f16.f32 "
        "{%0,%1,%2,%3}, {%4,%5,%6,%7}, {%8,%9}, {%0,%1,%2,%3};"
        : "+f"(d[0]), "+f"(d[1]), "+f"(d[2]), "+f"(d[3])
        : "r"(a[0]), "r"(a[1]), "r"(a[2]), "r"(a[3]), "r"(b[0]), "r"(b[1]));
}
__device__ __forceinline__ uint32_t packh2(float lo, float hi) {
    __half2 h = __floats2half2_rn(lo, hi);
    return *(uint32_t*)&h;
}
__device__ __forceinline__ uint32_t packresh2(float lo, float hi) {
    float rl = lo - __half2float(__float2half_rn(lo));
    float rh = hi - __half2float(__float2half_rn(hi));
    return packh2(rl, rh);
}
__device__ __forceinline__ uint32_t h2exp2(uint32_t x) {
    uint32_t r;
    asm("ex2.approx.f16x2 %0, %1;" : "=r"(r) : "r"(x));
    return r;
}

// ============================ scratch ============================
#define ACT_SZ ((size_t)M_ROWS * E_DIM)
#define W_SZ   ((size_t)E_DIM * E_DIM)
__device__ __half g_aq_h[ACT_SZ], g_aq_l[ACT_SZ];   // also reused: flash O hi/lo
__device__ __half g_ak_h[ACT_SZ];
__device__ __half g_av_h[ACT_SZ];
__device__ __half g_wq_h[W_SZ], g_wk_h[W_SZ], g_wv_h[W_SZ], g_wo_h[W_SZ];
#define BHTD ((size_t)B_DIM * H_DIM * L_DIM * HD)
__device__ __half g_Qh[BHTD];
__device__ __half g_Kh[BHTD];
__device__ __half g_Vh[BHTD];

// ==================== fused fp32 -> fp16 split (hi only) ====================
__global__ void __launch_bounds__(256)
split_all(const float* __restrict__ q,  const float* __restrict__ k,
          const float* __restrict__ v,  const float* __restrict__ wq,
          const float* __restrict__ wk, const float* __restrict__ wv,
          const float* __restrict__ wo,
          __half* aqh, __half* akh, __half* avh,
          __half* wqh, __half* wkh, __half* wvh, __half* woh)
{
    const int j = blockIdx.y;
    const float* src = (j == 0) ? q : (j == 1) ? k : (j == 2) ? v
                     : (j == 3) ? wq : (j == 4) ? wk : (j == 5) ? wv : wo;
    __half* hi = (j == 0) ? aqh : (j == 1) ? akh : (j == 2) ? avh
               : (j == 3) ? wqh : (j == 4) ? wkh : (j == 5) ? wvh : woh;
    const int reps = (j < 3) ? 4 : 1;

    for (int r = 0; r < reps; r++) {
        int i = (r * 1024 + blockIdx.x) * 256 + threadIdx.x;
        float4 vv = ((const float4*)src)[i];
        uint2 uh = {packh2(vv.x, vv.y), packh2(vv.z, vv.w)};
        ((uint2*)hi)[i] = uh;
    }
}

// ==================== GEMM core (BK=64, templated pass count) ==========
#define BK        64
#define ROW_PADB  72
#define TILE_B    (128 * ROW_PADB * 2)        // 18432
#define NCHUNK    (E_DIM / BK)                // 16
#define GEMM_SMEM1 (2 * 2 * TILE_B)           // 73728  (qkv, single pass)
#define GEMM_SMEM2 (2 * 3 * TILE_B)           // 110592 (o, two pass)

template<int NT>
__device__ __forceinline__ void gemm_core(
    const __half* __restrict__ Ah, const __half* __restrict__ Al,
    const __half* __restrict__ Wh,
    uint32_t sb, int m0, int n0, int tid, float acc[2][8][4])
{
    const int STAGE = NT * TILE_B;
    const int wid  = tid >> 5;
    const int lane = tid & 31;
    const int wm = (wid & 3) * 32;
    const int wn = (wid >> 2) * 64;

    auto prefetch = [&](int c, int buf) {
        const int k0 = c * BK;
#pragma unroll
        for (int it = 0; it < NT * 4; it++) {
            int idx  = it * 256 + tid;
            int tile = idx >> 10;
            int i    = idx & 1023;
            int row  = i >> 3;
            int ch   = i & 7;
            const __half* base =
                (tile == 0) ? Ah : (NT == 3 && tile == 1) ? Al : Wh;
            int grow = (tile < NT - 1 ? m0 : n0) + row;
            const __half* gp = base + (size_t)grow * E_DIM + k0 + ch * 8;
            uint32_t dst = sb + buf * STAGE + tile * TILE_B + row * (ROW_PADB * 2) + ch * 16;
            cp_async16(dst, gp);
        }
        CP_COMMIT();
    };

    prefetch(0, 0);

    const int arow = lane & 15;
    const int akh  = (lane >> 4) * 8;
    const int bg = lane >> 3;
    const int br = lane & 7;

    for (int c = 0; c < NCHUNK; c++) {
        const int buf = c & 1;
        CP_WAIT(0);
        __syncthreads();
        if (c + 1 < NCHUNK) prefetch(c + 1, buf ^ 1);

        const uint32_t st = sb + buf * STAGE;
        const uint32_t stB = st + (NT - 1) * TILE_B;
#pragma unroll
        for (int ks = 0; ks < 4; ks++) {
            const int kb = ks * 16;
            uint32_t ah[2][4], al[2][4];
#pragma unroll
            for (int mi = 0; mi < 2; mi++) {
                uint32_t addr = st +
                    (wm + mi * 16 + arow) * (ROW_PADB * 2) + (kb + akh) * 2;
                ldmatrix_x4(ah[mi][0], ah[mi][1], ah[mi][2], ah[mi][3], addr);
                if (NT == 3) {
                    addr += TILE_B;
                    ldmatrix_x4(al[mi][0], al[mi][1], al[mi][2], al[mi][3], addr);
                }
            }
            uint32_t bhv[8][2];
#pragma unroll
            for (int nq = 0; nq < 4; nq++) {
                uint32_t addr = stB +
                    (wn + nq * 16 + (bg >> 1) * 8 + br) * (ROW_PADB * 2) + (kb + (bg & 1) * 8) * 2;
                uint32_t r0, r1, r2, r3;
                ldmatrix_x4(r0, r1, r2, r3, addr);
                bhv[2 * nq][0] = r0; bhv[2 * nq][1] = r1;
                bhv[2 * nq + 1][0] = r2; bhv[2 * nq + 1][1] = r3;
            }
#pragma unroll
            for (int mi = 0; mi < 2; mi++)
#pragma unroll
                for (int ni = 0; ni < 8; ni++)
                    mma_f16(acc[mi][ni], ah[mi], bhv[ni]);   // hi pass
            if (NT == 3) {
#pragma unroll
                for (int mi = 0; mi < 2; mi++)
#pragma unroll
                    for (int ni = 0; ni < 8; ni++)
                        mma_f16(acc[mi][ni], al[mi], bhv[ni]);   // lo pass
            }
        }
    }
}

// ---- batched QKV projection (single-pass): z=0 Q(+rope, pre-scaled), z=1 K(+rope), z=2 V ----
#define SCALE2F (0.125f * 1.4426950408889634f)

__global__ void __launch_bounds__(256, 2)
mma_gemm_qkv(const __half* __restrict__ aqh, const __half* __restrict__ akh,
             const __half* __restrict__ avh,
             const __half* __restrict__ wqh, const __half* __restrict__ wkh,
             const __half* __restrict__ wvh,
             const float* __restrict__ bq, const float* __restrict__ bk,
             const float* __restrict__ bv,
             __half* __restrict__ qh, __half* __restrict__ kh, __half* __restrict__ vh)
{
    extern __shared__ char smem[];
    const uint32_t sb = smem_to_u32(smem);
    const int tid = threadIdx.x;
    const int z = blockIdx.z;
    const int m0 = blockIdx.y * 128;
    const int n0 = blockIdx.x * 128;

    const __half* Ah = (z == 0) ? aqh : (z == 1) ? akh : avh;
    const __half* Wh = (z == 0) ? wqh : (z == 1) ? wkh : wvh;
    const float* bias = (z == 0) ? bq : (z == 1) ? bk : bv;
    __half* outh = (z == 0) ? qh : (z == 1) ? kh : vh;
    const bool rope = (z != 2);
    const float oscale = (z == 0) ? SCALE2F : 1.0f;

    float acc[2][8][4];
#pragma unroll
    for (int mi = 0; mi < 2; mi++)
#pragma unroll
        for (int ni = 0; ni < 8; ni++)
#pragma unroll
            for (int q = 0; q < 4; q++) acc[mi][ni][q] = 0.0f;

    gemm_core<2>(Ah, nullptr, Wh, sb, m0, n0, tid, acc);

    const int wid  = tid >> 5;
    const int lane = tid & 31;
    const int wm = (wid & 3) * 32;
    const int wn = (wid >> 2) * 64;
    const int cbase = n0 + wn + (lane & 3) * 2;
#pragma unroll
    for (int ni = 0; ni < 8; ni++) {
        const int c = cbase + ni * 8;
        const float b0 = bias[c], b1 = bias[c + 1];
        float freq = 0.0f;
        if (rope) {
            int d = c & (HD - 1);
            freq = powf(10000.0f, -(float)d / (float)HD);
        }
        const int h    = c >> 6;
        const int dcol = c & (HD - 1);
#pragma unroll
        for (int mi = 0; mi < 2; mi++) {
#pragma unroll
            for (int rg = 0; rg < 2; rg++) {
                int m = m0 + wm + mi * 16 + (lane >> 2) + rg * 8;
                float v0 = acc[mi][ni][2 * rg] + b0;
                float v1 = acc[mi][ni][2 * rg + 1] + b1;
                int l  = m >> 1;
                int bb = m & 1;
                if (rope) {
                    float sv, cv;
                    sincosf((float)l * freq, &sv, &cv);
                    float x1 = v0, x2 = v1;
                    v0 = x1 * cv - x2 * sv;
                    v1 = x1 * sv + x2 * cv;
                }
                v0 *= oscale;
                v1 *= oscale;
                size_t idx = (((size_t)bb * H_DIM + h) * L_DIM + l) * HD + dcol;
                *(uint32_t*)(outh + idx) = packh2(v0, v1);
            }
        }
    }
}

// ---- output projection (two-pass A hi/lo): fp32 out[m*E+n] ----
__global__ void __launch_bounds__(256, 2)
mma_gemm_o(const __half* __restrict__ Ah, const __half* __restrict__ Al,
           const __half* __restrict__ Wh,
           const float* __restrict__ bias, float* __restrict__ outf)
{
    extern __shared__ char smem[];
    const uint32_t sb = smem_to_u32(smem);
    const int tid = threadIdx.x;
    const int m0 = blockIdx.y * 128;
    const int n0 = blockIdx.x * 128;

    float acc[2][8][4];
#pragma unroll
    for (int mi = 0; mi < 2; mi++)
#pragma unroll
        for (int ni = 0; ni < 8; ni++)
#pragma unroll
            for (int q = 0; q < 4; q++) acc[mi][ni][q] = 0.0f;

    gemm_core<3>(Ah, Al, Wh, sb, m0, n0, tid, acc);

    const int wid  = tid >> 5;
    const int lane = tid & 31;
    const int wm = (wid & 3) * 32;
    const int wn = (wid >> 2) * 64;
    const int cbase = n0 + wn + (lane & 3) * 2;
#pragma unroll
    for (int ni = 0; ni < 8; ni++) {
        const int c = cbase + ni * 8;
        const float b0 = bias[c], b1 = bias[c + 1];
#pragma unroll
        for (int mi = 0; mi < 2; mi++) {
#pragma unroll
            for (int rg = 0; rg < 2; rg++) {
                int m = m0 + wm + mi * 16 + (lane >> 2) + rg * 8;
                float2 r = {acc[mi][ni][2 * rg] + b0, acc[mi][ni][2 * rg + 1] + b1};
                *(float2*)(outf + (size_t)m * E_DIM + c) = r;
            }
        }
    }
}

// ==================== flash attention (128-row KV chunks, two 64-halves) ====================
#define FA_ROWB   144
#define FA_QTILE  (128 * FA_ROWB)              // 18432 (Qh only)
#define FA_KT     (128 * FA_ROWB)              // K tile: 128 rows
#define FA_STAGE  (2 * FA_KT)                  // K + V = 36864
#define FA_SMEM   (FA_QTILE + 2 * FA_STAGE)    // 92160 -> 2 CTA/SM
#define FA_NC     (S_DIM / 128)                // 16 chunks

__global__ void __launch_bounds__(256, 2)
flash_attn_mma(const __half* __restrict__ Qh_g,
               const __half* __restrict__ Kh_g, const __half* __restrict__ Vh_g,
               const unsigned char* __restrict__ mask,
               __half* __restrict__ Oh_g, __half* __restrict__ Ol_g)
{
    extern __shared__ char smem[];
    const uint32_t sb = smem_to_u32(smem);
    const int tid = threadIdx.x, lane = tid & 31, wid = tid >> 5;
    const int bh = blockIdx.y, b = bh >> 4, h = bh & 15;
    const int l0 = blockIdx.x * 128;
    const int wm = wid * 16;

    const size_t goff = (size_t)bh * L_DIM * HD;

    // Q hi tile
#pragma unroll
    for (int it = 0; it < 4; it++) {
        int idx = it * 256 + tid;
        int row = idx >> 3, ch = idx & 7;
        cp_async16(sb + row * FA_ROWB + ch * 16,
                   Qh_g + goff + (size_t)(l0 + row) * HD + ch * 8);
    }

    const __half* kvsrc[2] = {Kh_g + goff, Vh_g + goff};
    const uint32_t kvbase = sb + FA_QTILE;
    // 128-row K + 128-row V per chunk: 2048 16B slots = 8 iters
    auto prefetch_kv = [&](int c, int buf) {
        int s0 = c * 128;
#pragma unroll
        for (int it = 0; it < 8; it++) {
            int idx = it * 256 + tid;
            int tile = idx >> 10, i = idx & 1023, row = i >> 3, ch = i & 7;
            cp_async16(kvbase + buf * FA_STAGE + tile * FA_KT + row * FA_ROWB + ch * 16,
                       kvsrc[tile] + (size_t)(s0 + row) * HD + ch * 8);
        }
        CP_COMMIT();
    };
    prefetch_kv(0, 0);   // commits Q loads too

    float o_acc[8][4];
#pragma unroll
    for (int ni = 0; ni < 8; ni++)
#pragma unroll
        for (int q = 0; q < 4; q++) o_acc[ni][q] = 0.0f;
    float mi0 = -CUDART_INF_F, mi1 = -CUDART_INF_F, li0 = 0.0f, li1 = 0.0f;

    const int arow = lane & 15, akh = (lane >> 4) * 8;
    const int bg = lane >> 3, br = lane & 7;
    const int brow_off = (bg >> 1) * 8 + br;
    const int bk_off   = (bg & 1) * 8;
    const int trow_off = ((lane >> 3) & 1) * 8 + (lane & 7);
    const int tcol_off = (lane >> 4) * 8;
    const uint32_t ones2 = packh2(1.0f, 1.0f);
    const uint32_t bones[2] = {ones2, ones2};

    uint32_t qfh[4][4];

    for (int c = 0; c < FA_NC; c++) {
        const int buf = c & 1;

        CP_WAIT(0);
        __syncthreads();
        if (c + 1 < FA_NC) prefetch_kv(c + 1, buf ^ 1);

        if (c == 0) {
#pragma unroll
            for (int ks = 0; ks < 4; ks++) {
                uint32_t qaddr = sb + (wm + arow) * FA_ROWB + (ks * 16 + akh) * 2;
                ldmatrix_x4(qfh[ks][0], qfh[ks][1], qfh[ks][2], qfh[ks][3], qaddr);
            }
        }

        // two 64-row halves, identical order to the previous 64-chunk version
#pragma unroll
        for (int hh = 0; hh < 2; hh++) {
            const uint32_t sK = kvbase + buf * FA_STAGE + hh * 64 * FA_ROWB;
            const uint32_t sV = sK + FA_KT;
            const int s0c = c * 128 + hh * 64;

            uchar2 mk[8];
#pragma unroll
            for (int ni = 0; ni < 8; ni++)
                mk[ni] = *(const uchar2*)(mask + (size_t)b * S_DIM + s0c + ni * 8 + (lane & 3) * 2);

            float s[8][4];
#pragma unroll
            for (int ni = 0; ni < 8; ni++)
#pragma unroll
                for (int q = 0; q < 4; q++) s[ni][q] = 0.0f;

            // GEMM1: S = Qh * Kh^T
#pragma unroll
            for (int ks = 0; ks < 4; ks++) {
                const int kb = ks * 16;
#pragma unroll
                for (int nq = 0; nq < 4; nq++) {
                    uint32_t kaddr = sK + (nq * 16 + brow_off) * FA_ROWB + (kb + bk_off) * 2;
                    uint32_t k0, k1, k2, k3;
                    ldmatrix_x4(k0, k1, k2, k3, kaddr);
                    uint32_t kh0[2] = {k0, k1}, kh1[2] = {k2, k3};
                    mma_f16(s[2 * nq],     qfh[ks], kh0);
                    mma_f16(s[2 * nq + 1], qfh[ks], kh1);
                }
            }

            float mlo = -CUDART_INF_F, mhi = -CUDART_INF_F;
#pragma unroll
            for (int ni = 0; ni < 8; ni++) {
                float v0 = mk[ni].x ? -CUDART_INF_F : s[ni][0];
                float v1 = mk[ni].y ? -CUDART_INF_F : s[ni][1];
                float v2 = mk[ni].x ? -CUDART_INF_F : s[ni][2];
                float v3 = mk[ni].y ? -CUDART_INF_F : s[ni][3];
                s[ni][0] = v0; s[ni][1] = v1; s[ni][2] = v2; s[ni][3] = v3;
                mlo = fmaxf(mlo, fmaxf(v0, v1));
                mhi = fmaxf(mhi, fmaxf(v2, v3));
            }
            mlo = fmaxf(mlo, __shfl_xor_sync(0xffffffffu, mlo, 1));
            mlo = fmaxf(mlo, __shfl_xor_sync(0xffffffffu, mlo, 2));
            mhi = fmaxf(mhi, __shfl_xor_sync(0xffffffffu, mhi, 1));
            mhi = fmaxf(mhi, __shfl_xor_sync(0xffffffffu, mhi, 2));

            float mn0 = fmaxf(mi0, mlo), mn1 = fmaxf(mi1, mhi);
            float a0 = exp2f(mi0 - mn0), a1 = exp2f(mi1 - mn1);
            mi0 = mn0; mi1 = mn1;
#pragma unroll
            for (int ni = 0; ni < 8; ni++) {
                o_acc[ni][0] *= a0; o_acc[ni][1] *= a0;
                o_acc[ni][2] *= a1; o_acc[ni][3] *= a1;
            }

            float sum_acc[4] = {0.0f, 0.0f, 0.0f, 0.0f};
#pragma unroll
            for (int ks = 0; ks < 4; ks++) {
                uint32_t pah[4];
                pah[0] = h2exp2(packh2(s[2 * ks][0] - mn0,     s[2 * ks][1] - mn0));
                pah[1] = h2exp2(packh2(s[2 * ks][2] - mn1,     s[2 * ks][3] - mn1));
                pah[2] = h2exp2(packh2(s[2 * ks + 1][0] - mn0, s[2 * ks + 1][1] - mn0));
                pah[3] = h2exp2(packh2(s[2 * ks + 1][2] - mn1, s[2 * ks + 1][3] - mn1));
                mma_f16(sum_acc, pah, bones);
#pragma unroll
                for (int nb = 0; nb < 4; nb++) {
                    uint32_t vaddr = sV + (ks * 16 + trow_off) * FA_ROWB + (nb * 16 + tcol_off) * 2;
                    uint32_t v0, v1, v2, v3;
                    ldmatrix_x4_trans(v0, v1, v2, v3, vaddr);
                    uint32_t vh0[2] = {v0, v1}, vh1[2] = {v2, v3};
                    mma_f16(o_acc[2 * nb],     pah, vh0);
                    mma_f16(o_acc[2 * nb + 1], pah, vh1);
                }
            }
            li0 = li0 * a0 + sum_acc[0];
            li1 = li1 * a1 + sum_acc[2];
        }
    }

    const float inv0 = 1.0f / li0, inv1 = 1.0f / li1;
    const int r0 = lane >> 2;
    const int m0g = ((l0 + wm + r0) << 1) | b;
    const int m1g = ((l0 + wm + r0 + 8) << 1) | b;
#pragma unroll
    for (int ni = 0; ni < 8; ni++) {
        int cg = h * HD + ni * 8 + (lane & 3) * 2;
        float v00 = o_acc[ni][0] * inv0, v01 = o_acc[ni][1] * inv0;
        float v10 = o_acc[ni][2] * inv1, v11 = o_acc[ni][3] * inv1;
        *(uint32_t*)(Oh_g + (size_t)m0g * E_DIM + cg) = packh2(v00, v01);
        *(uint32_t*)(Ol_g + (size_t)m0g * E_DIM + cg) = packresh2(v00, v01);
        *(uint32_t*)(Oh_g + (size_t)m1g * E_DIM + cg) = packh2(v10, v11);
        *(uint32_t*)(Ol_g + (size_t)m1g * E_DIM + cg) = packresh2(v10, v11);
    }
}

// ============================================================================
// launch
// ============================================================================
extern "C" void kernel_launch(void* const* d_in, const int* in_sizes, int n_in,
                              void* d_out, int out_size)
{
    const float* query = (const float*)d_in[0];
    const float* key   = (const float*)d_in[1];
    const float* value = (const float*)d_in[2];
    const unsigned char* mask = (const unsigned char*)d_in[3];
    const float* Wq = (const float*)d_in[4];
    const float* bq = (const float*)d_in[5];
    const float* Wk = (const float*)d_in[6];
    const float* bk = (const float*)d_in[7];
    const float* Wv = (const float*)d_in[8];
    const float* bv = (const float*)d_in[9];
    const float* Wo = (const float*)d_in[10];
    const float* bo = (const float*)d_in[11];
    float* out = (float*)d_out;

    __half *aqh, *aql, *akh, *avh;
    __half *wqh, *wkh, *wvh, *woh;
    __half *qh, *kh, *vh;
    cudaGetSymbolAddress((void**)&aqh, g_aq_h); cudaGetSymbolAddress((void**)&aql, g_aq_l);
    cudaGetSymbolAddress((void**)&akh, g_ak_h);
    cudaGetSymbolAddress((void**)&avh, g_av_h);
    cudaGetSymbolAddress((void**)&wqh, g_wq_h); cudaGetSymbolAddress((void**)&wkh, g_wk_h);
    cudaGetSymbolAddress((void**)&wvh, g_wv_h); cudaGetSymbolAddress((void**)&woh, g_wo_h);
    cudaGetSymbolAddress((void**)&qh, g_Qh);
    cudaGetSymbolAddress((void**)&kh, g_Kh); cudaGetSymbolAddress((void**)&vh, g_Vh);

    cudaFuncSetAttribute(mma_gemm_qkv, cudaFuncAttributeMaxDynamicSharedMemorySize, GEMM_SMEM1);
    cudaFuncSetAttribute(mma_gemm_o,   cudaFuncAttributeMaxDynamicSharedMemorySize, GEMM_SMEM2);
    cudaFuncSetAttribute(flash_attn_mma, cudaFuncAttributeMaxDynamicSharedMemorySize, FA_SMEM);

    // hi-only splits (3 activations + 4 weights)
    dim3 sgrid(1024, 7);
    split_all<<<sgrid, 256>>>(query, key, value, Wq, Wk, Wv, Wo,
                              aqh, akh, avh, wqh, wkh, wvh, woh);

    // batched QKV projections, single-pass (+RoPE on Q,K; Q pre-scaled)
    dim3 qkv_grid(E_DIM / 128, M_ROWS / 128, 3);   // (8, 32, 3)
    mma_gemm_qkv<<<qkv_grid, 256, GEMM_SMEM1>>>(
        aqh, akh, avh, wqh, wkh, wvh, bq, bk, bv, qh, kh, vh);

    // attention -> O hi/lo into g_aq_h / g_aq_l
    dim3 agrid(L_DIM / 128, B_DIM * H_DIM);        // (16, 32)
    flash_attn_mma<<<agrid, 256, FA_SMEM>>>(qh, kh, vh, mask, aqh, aql);

    // output projection (two-pass) -> d_out fp32
    dim3 ogrid(E_DIM / 128, M_ROWS / 128);
    mma_gemm_o<<<ogrid, 256, GEMM_SMEM2>>>(aqh, aql, woh, bo, out);
}